// round 1
// baseline (speedup 1.0000x reference)
#include <cuda_runtime.h>
#include <math.h>

#define BB 2
#define LL 2048
#define DD 1024
#define HH 16
#define HD 64
#define MM (BB*LL)        // 4096
#define N_QKV (3*DD)      // 3072

// Scratch (allocation-free rule: __device__ globals)
__device__ float g_q[BB*HH*LL*HD];   // (b,h,l,d)
__device__ float g_k[BB*HH*LL*HD];
__device__ float g_v[BB*HH*LL*HD];
__device__ float g_o[MM*DD];         // (b,l, h*64+d)
__device__ float g_gate[BB*LL];

// ---------------------------------------------------------------------------
// QKV GEMM: C[m][n] = sum_k X[m][k] * W[n][k];  M=4096, N=3072, K=1024
// 128x128 block tile, 8-deep K slab, 256 threads, 8x8 per thread (4+4 split).
// Epilogue scatters into q/k/v with (b,h,l,d) layout.
// ---------------------------------------------------------------------------
__global__ __launch_bounds__(256) void qkv_gemm_kernel(
    const float* __restrict__ X, const float* __restrict__ W)
{
    __shared__ float As[8][128];
    __shared__ float Bs[8][128];
    const int bm = blockIdx.y * 128;
    const int bn = blockIdx.x * 128;
    const int tid = threadIdx.x;
    const int ty = tid >> 4, tx = tid & 15;
    const int lr = tid >> 1;
    const int lc = (tid & 1) << 2;
    const float* Ap = X + (size_t)(bm + lr) * 1024 + lc;
    const float* Bp = W + (size_t)(bn + lr) * 1024 + lc;

    float acc[8][8];
#pragma unroll
    for (int i = 0; i < 8; i++)
#pragma unroll
        for (int j = 0; j < 8; j++) acc[i][j] = 0.f;

    for (int k0 = 0; k0 < 1024; k0 += 8) {
        float4 av = *(const float4*)(Ap + k0);
        float4 bv = *(const float4*)(Bp + k0);
        As[lc+0][lr] = av.x; As[lc+1][lr] = av.y; As[lc+2][lr] = av.z; As[lc+3][lr] = av.w;
        Bs[lc+0][lr] = bv.x; Bs[lc+1][lr] = bv.y; Bs[lc+2][lr] = bv.z; Bs[lc+3][lr] = bv.w;
        __syncthreads();
#pragma unroll
        for (int kk = 0; kk < 8; kk++) {
            float a[8], b[8];
            *(float4*)&a[0] = *(const float4*)&As[kk][ty*4];
            *(float4*)&a[4] = *(const float4*)&As[kk][64 + ty*4];
            *(float4*)&b[0] = *(const float4*)&Bs[kk][tx*4];
            *(float4*)&b[4] = *(const float4*)&Bs[kk][64 + tx*4];
#pragma unroll
            for (int i = 0; i < 8; i++)
#pragma unroll
                for (int j = 0; j < 8; j++) acc[i][j] = fmaf(a[i], b[j], acc[i][j]);
        }
        __syncthreads();
    }

#pragma unroll
    for (int i = 0; i < 8; i++) {
        int m  = bm + ty*4 + (i & 3) + ((i >> 2) << 6);
        int bb = m >> 11;
        int l  = m & 2047;
#pragma unroll
        for (int j = 0; j < 8; j++) {
            int n = bn + tx*4 + (j & 3) + ((j >> 2) << 6);
            int which = n >> 10;
            int h = (n >> 6) & 15;
            int d = n & 63;
            float* dst = (which == 0) ? g_q : ((which == 1) ? g_k : g_v);
            dst[((size_t)(bb*HH + h)*LL + l)*HD + d] = acc[i][j];
        }
    }
}

// ---------------------------------------------------------------------------
// Gate: gate[b,l] = softmax_l( sqrt(Gr^2+Gi^2+eps) / exp(log_temp) ) * gate_scale
// One block per batch, 256 threads * 8 elems.
// ---------------------------------------------------------------------------
__global__ __launch_bounds__(256) void gate_kernel(
    const float* __restrict__ G, const float* __restrict__ gs_p,
    const float* __restrict__ lt_p)
{
    __shared__ float sm[256];
    const int b   = blockIdx.x;
    const int tid = threadIdx.x;
    const float inv_temp = __expf(-lt_p[0]);

    float z[8];
    float mx = -INFINITY;
#pragma unroll
    for (int i = 0; i < 8; i++) {
        int l = i*256 + tid;
        float gr = G[(b*LL + l)*2 + 0];
        float gi = G[(b*LL + l)*2 + 1];
        z[i] = sqrtf(gr*gr + gi*gi + 1e-7f) * inv_temp;
        mx = fmaxf(mx, z[i]);
    }
    sm[tid] = mx; __syncthreads();
    for (int s = 128; s > 0; s >>= 1) {
        if (tid < s) sm[tid] = fmaxf(sm[tid], sm[tid + s]);
        __syncthreads();
    }
    const float gmax = sm[0];
    __syncthreads();

    float e[8];
    float lsum = 0.f;
#pragma unroll
    for (int i = 0; i < 8; i++) { e[i] = __expf(z[i] - gmax); lsum += e[i]; }
    sm[tid] = lsum; __syncthreads();
    for (int s = 128; s > 0; s >>= 1) {
        if (tid < s) sm[tid] += sm[tid + s];
        __syncthreads();
    }
    const float inv_sum = 1.f / sm[0];
    const float gs = gs_p[0];
#pragma unroll
    for (int i = 0; i < 8; i++)
        g_gate[b*LL + i*256 + tid] = e[i] * inv_sum * gs;
}

// ---------------------------------------------------------------------------
// Flash attention, fp32. Grid: (L/64, B*H). 256 threads (16x16).
// BQ=64 queries per block, BK=32 keys per tile, hd=64.
// Qs/Ks stored d-major (transposed) for conflict-free LDS.128 in the S GEMM.
// Online softmax state per thread covers 4 query rows; row reductions via
// width-16 xor shuffles (tx axis). P goes through padded smem for PV GEMM.
// Epilogue fuses 1/l and the scattering gate (per-query scale).
// ---------------------------------------------------------------------------
__global__ __launch_bounds__(256) void attn_kernel()
{
    __shared__ float Qs[64][64];   // [d][q], pre-scaled by 1/sqrt(hd)
    __shared__ float Ks[64][32];   // [d][k]
    __shared__ float Vs[32][64];   // [k][d]
    __shared__ float Ps[32][65];   // [k][q] (+1 pad: 2-way max on stores)

    const int bh    = blockIdx.y;           // b*16 + h
    const int qbase = blockIdx.x * 64;
    const int tid   = threadIdx.x;
    const int ty    = tid >> 4, tx = tid & 15;

    const float* Qg = g_q + (size_t)bh * LL * HD;
    const float* Kg = g_k + (size_t)bh * LL * HD;
    const float* Vg = g_v + (size_t)bh * LL * HD;

    // Load Q tile transposed + scaled
    {
        int q  = tid & 63;
        int d0 = (tid >> 6) << 2;           // 0,4,8,12
#pragma unroll
        for (int it = 0; it < 4; it++) {
            int d = d0 + it*16;
            float4 v = *(const float4*)(Qg + (size_t)(qbase + q)*HD + d);
            Qs[d+0][q] = v.x*0.125f; Qs[d+1][q] = v.y*0.125f;
            Qs[d+2][q] = v.z*0.125f; Qs[d+3][q] = v.w*0.125f;
        }
    }

    float m_i[4], l_i[4], acc[4][4];
#pragma unroll
    for (int i = 0; i < 4; i++) {
        m_i[i] = -INFINITY; l_i[i] = 0.f;
#pragma unroll
        for (int j = 0; j < 4; j++) acc[i][j] = 0.f;
    }
    __syncthreads();

    for (int kt = 0; kt < LL/32; kt++) {
        const int kbase = kt * 32;

        // K tile transposed: conflict-free smem stores (k = lane)
        {
            int k  = tid & 31;
            int d0 = (tid >> 5) << 2;       // 0..28 step 4
#pragma unroll
            for (int it = 0; it < 2; it++) {
                int d = d0 + it*32;
                float4 v = *(const float4*)(Kg + (size_t)(kbase + k)*HD + d);
                Ks[d+0][k] = v.x; Ks[d+1][k] = v.y; Ks[d+2][k] = v.z; Ks[d+3][k] = v.w;
            }
        }
        // V tile direct (coalesced)
        {
            int r = tid >> 4;
            int c = (tid & 15) << 2;
#pragma unroll
            for (int it = 0; it < 2; it++) {
                int k = r + it*16;
                *(float4*)&Vs[k][c] = *(const float4*)(Vg + (size_t)(kbase + k)*HD + c);
            }
        }
        __syncthreads();

        // S[q=ty*4+i][k=tx*2+j] = sum_d Qs[d][q]*Ks[d][k]
        float s[4][2];
#pragma unroll
        for (int i = 0; i < 4; i++) { s[i][0] = 0.f; s[i][1] = 0.f; }
#pragma unroll 16
        for (int dd = 0; dd < 64; dd++) {
            float a[4];
            *(float4*)&a[0] = *(const float4*)&Qs[dd][ty*4];
            float b0 = Ks[dd][tx*2 + 0];
            float b1 = Ks[dd][tx*2 + 1];
#pragma unroll
            for (int i = 0; i < 4; i++) {
                s[i][0] = fmaf(a[i], b0, s[i][0]);
                s[i][1] = fmaf(a[i], b1, s[i][1]);
            }
        }

        // Online softmax (rows reduced across the 16 tx lanes)
        float p[4][2];
#pragma unroll
        for (int i = 0; i < 4; i++) {
            float rm = fmaxf(s[i][0], s[i][1]);
#pragma unroll
            for (int o = 8; o > 0; o >>= 1)
                rm = fmaxf(rm, __shfl_xor_sync(0xffffffffu, rm, o));
            float mn   = fmaxf(m_i[i], rm);
            float corr = __expf(m_i[i] - mn);
            m_i[i] = mn;
            p[i][0] = __expf(s[i][0] - mn);
            p[i][1] = __expf(s[i][1] - mn);
            float rs = p[i][0] + p[i][1];
#pragma unroll
            for (int o = 8; o > 0; o >>= 1)
                rs += __shfl_xor_sync(0xffffffffu, rs, o);
            l_i[i] = l_i[i]*corr + rs;
#pragma unroll
            for (int j = 0; j < 4; j++) acc[i][j] *= corr;
        }

        // Stage P into smem [k][q]
#pragma unroll
        for (int i = 0; i < 4; i++) {
            Ps[tx*2 + 0][ty*4 + i] = p[i][0];
            Ps[tx*2 + 1][ty*4 + i] = p[i][1];
        }
        __syncthreads();

        // O[q=ty*4+i][d=tx*4+j] += sum_k Ps[k][q]*Vs[k][d]
#pragma unroll 8
        for (int kk = 0; kk < 32; kk++) {
            float a0 = Ps[kk][ty*4+0], a1 = Ps[kk][ty*4+1];
            float a2 = Ps[kk][ty*4+2], a3 = Ps[kk][ty*4+3];
            float bb[4];
            *(float4*)&bb[0] = *(const float4*)&Vs[kk][tx*4];
#pragma unroll
            for (int j = 0; j < 4; j++) {
                acc[0][j] = fmaf(a0, bb[j], acc[0][j]);
                acc[1][j] = fmaf(a1, bb[j], acc[1][j]);
                acc[2][j] = fmaf(a2, bb[j], acc[2][j]);
                acc[3][j] = fmaf(a3, bb[j], acc[3][j]);
            }
        }
        __syncthreads();
    }

    // Epilogue: 1/l, gate, scatter to (b, l, h*64+d)
    const int b = bh >> 4, h = bh & 15;
#pragma unroll
    for (int i = 0; i < 4; i++) {
        int q = qbase + ty*4 + i;
        float sc = (1.0f / l_i[i]) * g_gate[b*LL + q];
        float* dst = g_o + ((size_t)(b*LL + q))*DD + h*HD + tx*4;
#pragma unroll
        for (int j = 0; j < 4; j++) dst[j] = acc[i][j] * sc;
    }
}

// ---------------------------------------------------------------------------
// Out GEMM: C[m][n] = sum_k g_o[m][k]*W[n][k] + bias[n];  M=4096, N=1024, K=1024
// ---------------------------------------------------------------------------
__global__ __launch_bounds__(256) void out_gemm_kernel(
    const float* __restrict__ W, const float* __restrict__ bias,
    float* __restrict__ C)
{
    __shared__ float As[8][128];
    __shared__ float Bs[8][128];
    const int bm = blockIdx.y * 128;
    const int bn = blockIdx.x * 128;
    const int tid = threadIdx.x;
    const int ty = tid >> 4, tx = tid & 15;
    const int lr = tid >> 1;
    const int lc = (tid & 1) << 2;
    const float* Ap = g_o + (size_t)(bm + lr) * 1024 + lc;
    const float* Bp = W   + (size_t)(bn + lr) * 1024 + lc;

    float acc[8][8];
#pragma unroll
    for (int i = 0; i < 8; i++)
#pragma unroll
        for (int j = 0; j < 8; j++) acc[i][j] = 0.f;

    for (int k0 = 0; k0 < 1024; k0 += 8) {
        float4 av = *(const float4*)(Ap + k0);
        float4 bv = *(const float4*)(Bp + k0);
        As[lc+0][lr] = av.x; As[lc+1][lr] = av.y; As[lc+2][lr] = av.z; As[lc+3][lr] = av.w;
        Bs[lc+0][lr] = bv.x; Bs[lc+1][lr] = bv.y; Bs[lc+2][lr] = bv.z; Bs[lc+3][lr] = bv.w;
        __syncthreads();
#pragma unroll
        for (int kk = 0; kk < 8; kk++) {
            float a[8], b[8];
            *(float4*)&a[0] = *(const float4*)&As[kk][ty*4];
            *(float4*)&a[4] = *(const float4*)&As[kk][64 + ty*4];
            *(float4*)&b[0] = *(const float4*)&Bs[kk][tx*4];
            *(float4*)&b[4] = *(const float4*)&Bs[kk][64 + tx*4];
#pragma unroll
            for (int i = 0; i < 8; i++)
#pragma unroll
                for (int j = 0; j < 8; j++) acc[i][j] = fmaf(a[i], b[j], acc[i][j]);
        }
        __syncthreads();
    }

#pragma unroll
    for (int i = 0; i < 8; i++) {
        int m = bm + ty*4 + (i & 3) + ((i >> 2) << 6);
#pragma unroll
        for (int j = 0; j < 8; j++) {
            int n = bn + tx*4 + (j & 3) + ((j >> 2) << 6);
            C[(size_t)m * 1024 + n] = acc[i][j] + bias[n];
        }
    }
}

// ---------------------------------------------------------------------------
extern "C" void kernel_launch(void* const* d_in, const int* in_sizes, int n_in,
                              void* d_out, int out_size)
{
    const float* x    = (const float*)d_in[0];
    const float* G    = (const float*)d_in[1];
    const float* qkvw = (const float*)d_in[2];
    const float* outw = (const float*)d_in[3];
    const float* outb = (const float*)d_in[4];
    const float* gsc  = (const float*)d_in[5];
    const float* ltm  = (const float*)d_in[6];
    float* out = (float*)d_out;

    dim3 g1(N_QKV/128, MM/128);       // (24, 32)
    qkv_gemm_kernel<<<g1, 256>>>(x, qkvw);

    gate_kernel<<<BB, 256>>>(G, gsc, ltm);

    dim3 g2(LL/64, BB*HH);            // (32, 32)
    attn_kernel<<<g2, 256>>>();

    dim3 g3(DD/128, MM/128);          // (8, 32)
    out_gemm_kernel<<<g3, 256>>>(outw, outb, out);
}

// round 2
// speedup vs baseline: 2.7036x; 2.7036x over previous
#include <cuda_runtime.h>
#include <math.h>

#define BB 2
#define LL 2048
#define DD 1024
#define HH 16
#define HD 64
#define MM (BB*LL)        // 4096
#define N_QKV (3*DD)      // 3072

// Scratch (allocation-free rule: __device__ globals)
__device__ float g_q[BB*HH*LL*HD];   // (b,h,l,d)  tf32-rounded, q pre-scaled by 1/8
__device__ float g_k[BB*HH*LL*HD];   // tf32-rounded
__device__ float g_v[BB*HH*LL*HD];   // tf32-rounded
__device__ float g_o[MM*DD];         // (b,l,h*64+d) tf32-rounded attention output
__device__ float g_gate[BB*LL];
__device__ float g_xt[MM*DD];        // tf32-rounded x
__device__ float g_wq[N_QKV*DD];     // tf32-rounded qkv_w
__device__ float g_wo[DD*DD];        // tf32-rounded out_w

// ---------------------------------------------------------------------------
// helpers
// ---------------------------------------------------------------------------
__device__ __forceinline__ unsigned f2tf32(float f) {
    unsigned u;
    asm("cvt.rna.tf32.f32 %0, %1;" : "=r"(u) : "f"(f));
    return u;
}

__device__ __forceinline__ void mma_tf32(float c[4], const unsigned a[4], const unsigned b[2]) {
    asm("mma.sync.aligned.m16n8k8.row.col.f32.tf32.tf32.f32 "
        "{%0,%1,%2,%3}, {%4,%5,%6,%7}, {%8,%9}, {%0,%1,%2,%3};"
        : "+f"(c[0]), "+f"(c[1]), "+f"(c[2]), "+f"(c[3])
        : "r"(a[0]), "r"(a[1]), "r"(a[2]), "r"(a[3]), "r"(b[0]), "r"(b[1]));
}

// ---------------------------------------------------------------------------
// elementwise tf32 rounding (one pass per operand; paid once, not per reuse)
// ---------------------------------------------------------------------------
__global__ void cvt_tf32_kernel(const float* __restrict__ src, float* __restrict__ dst, int n) {
    int i = blockIdx.x * blockDim.x + threadIdx.x;
    if (i < n) dst[i] = __uint_as_float(f2tf32(src[i]));
}

// ---------------------------------------------------------------------------
// QKV GEMM (tensor core): C[m][n] = sum_k X[m][k]*W[n][k]
// M=4096, N=3072, K=1024. 128x128 block, 8 warps of 64x32, m16n8k8 tf32.
// Epilogue scatters tf32-rounded q(*0.125)/k/v into (b,h,l,d).
// ---------------------------------------------------------------------------
__device__ __forceinline__ void qkv_store(int m, int n, float v0, float v1) {
    int b = m >> 11, l = m & 2047;
    int which = n >> 10, h = (n >> 6) & 15, d = n & 63;
    float* dst = (which == 0) ? g_q : ((which == 1) ? g_k : g_v);
    if (which == 0) { v0 *= 0.125f; v1 *= 0.125f; }
    float2 val;
    val.x = __uint_as_float(f2tf32(v0));
    val.y = __uint_as_float(f2tf32(v1));
    *(float2*)(dst + ((size_t)((b << 4) + h) * LL + l) * HD + d) = val;
}

__global__ __launch_bounds__(256, 2) void qkv_gemm_tc() {
    __shared__ float As[128 * 20];
    __shared__ float Bs[128 * 20];
    const int tid = threadIdx.x, lane = tid & 31, wid = tid >> 5;
    const int wm = (wid & 1) << 6, wn = (wid >> 1) << 5;
    const int bm = blockIdx.y << 7, bn = blockIdx.x << 7;
    const int lr4 = lane >> 2, lc = lane & 3;

    float acc[4][4][4];
#pragma unroll
    for (int mt = 0; mt < 4; mt++)
#pragma unroll
        for (int nt = 0; nt < 4; nt++)
#pragma unroll
            for (int i = 0; i < 4; i++) acc[mt][nt][i] = 0.f;

    const int row = tid >> 2, kk = (tid & 3) << 2;
    const float* Ag = g_xt + (size_t)(bm + row) * DD + kk;
    const float* Bg = g_wq + (size_t)(bn + row) * DD + kk;

    for (int k0 = 0; k0 < DD; k0 += 16) {
        float4 a0 = *(const float4*)(Ag + k0);
        float4 a1 = *(const float4*)(Ag + k0 + (size_t)64 * DD);
        float4 b0 = *(const float4*)(Bg + k0);
        float4 b1 = *(const float4*)(Bg + k0 + (size_t)64 * DD);
        __syncthreads();
        *(float4*)&As[row * 20 + kk]        = a0;
        *(float4*)&As[(row + 64) * 20 + kk] = a1;
        *(float4*)&Bs[row * 20 + kk]        = b0;
        *(float4*)&Bs[(row + 64) * 20 + kk] = b1;
        __syncthreads();
        const unsigned* Au = (const unsigned*)As;
        const unsigned* Bu = (const unsigned*)Bs;
#pragma unroll
        for (int ks = 0; ks < 16; ks += 8) {
            unsigned a[4][4], b[4][2];
#pragma unroll
            for (int mt = 0; mt < 4; mt++) {
                int base = (wm + mt * 16 + lr4) * 20 + ks + lc;
                a[mt][0] = Au[base];       a[mt][1] = Au[base + 160];
                a[mt][2] = Au[base + 4];   a[mt][3] = Au[base + 164];
            }
#pragma unroll
            for (int nt = 0; nt < 4; nt++) {
                int bb = (wn + nt * 8 + lr4) * 20 + ks + lc;
                b[nt][0] = Bu[bb]; b[nt][1] = Bu[bb + 4];
            }
#pragma unroll
            for (int mt = 0; mt < 4; mt++)
#pragma unroll
                for (int nt = 0; nt < 4; nt++) mma_tf32(acc[mt][nt], a[mt], b[nt]);
        }
    }

#pragma unroll
    for (int mt = 0; mt < 4; mt++)
#pragma unroll
        for (int nt = 0; nt < 4; nt++) {
            int m = bm + wm + mt * 16 + lr4;
            int n = bn + wn + (nt << 3) + (lc << 1);
            qkv_store(m,     n, acc[mt][nt][0], acc[mt][nt][1]);
            qkv_store(m + 8, n, acc[mt][nt][2], acc[mt][nt][3]);
        }
}

// ---------------------------------------------------------------------------
// Gate: softmax over L of sqrt(Gr^2+Gi^2+eps)/temp, * gate_scale
// ---------------------------------------------------------------------------
__global__ __launch_bounds__(256) void gate_kernel(
    const float* __restrict__ G, const float* __restrict__ gs_p,
    const float* __restrict__ lt_p)
{
    __shared__ float sm[256];
    const int b = blockIdx.x, tid = threadIdx.x;
    const float inv_temp = __expf(-lt_p[0]);

    float z[8];
    float mx = -INFINITY;
#pragma unroll
    for (int i = 0; i < 8; i++) {
        int l = i * 256 + tid;
        float gr = G[(b * LL + l) * 2 + 0];
        float gi = G[(b * LL + l) * 2 + 1];
        z[i] = sqrtf(gr * gr + gi * gi + 1e-7f) * inv_temp;
        mx = fmaxf(mx, z[i]);
    }
    sm[tid] = mx; __syncthreads();
    for (int s = 128; s > 0; s >>= 1) {
        if (tid < s) sm[tid] = fmaxf(sm[tid], sm[tid + s]);
        __syncthreads();
    }
    const float gmax = sm[0];
    __syncthreads();

    float e[8]; float lsum = 0.f;
#pragma unroll
    for (int i = 0; i < 8; i++) { e[i] = __expf(z[i] - gmax); lsum += e[i]; }
    sm[tid] = lsum; __syncthreads();
    for (int s = 128; s > 0; s >>= 1) {
        if (tid < s) sm[tid] += sm[tid + s];
        __syncthreads();
    }
    const float inv_sum = 1.f / sm[0];
    const float gs = gs_p[0];
#pragma unroll
    for (int i = 0; i < 8; i++)
        g_gate[b * LL + i * 256 + tid] = e[i] * inv_sum * gs;
}

// ---------------------------------------------------------------------------
// Flash attention (tensor core). Grid (L/128, B*H), 256 threads / 8 warps.
// BQ=128 (16 rows/warp), BK=32, hd=64. Q frags register-resident.
// K natural [key][d] pad-68; V transposed [d][key] pad-36; P per-warp smem.
// Epilogue fuses 1/l + scattering gate + tf32 rounding for out-GEMM.
// ---------------------------------------------------------------------------
__global__ __launch_bounds__(256, 2) void attn_tc() {
    __shared__ float Ks[32 * 68];
    __shared__ float Vs[64 * 36];
    __shared__ float Ps[128 * 36];

    const int tid = threadIdx.x, lane = tid & 31, wid = tid >> 5;
    const int bh = blockIdx.y, qbase = blockIdx.x << 7;
    const int lr4 = lane >> 2, lc = lane & 3;
    const int rq = wid * 16 + lr4;              // warp-owned row (and rq+8)

    const float* Qg = g_q + ((size_t)bh * LL + qbase) * HD;
    const float* Kg = g_k + (size_t)bh * LL * HD;
    const float* Vg = g_v + (size_t)bh * LL * HD;

    // Preload Q fragments (already *0.125 and tf32-rounded by QKV epilogue)
    unsigned qf[8][4];
#pragma unroll
    for (int k = 0; k < 8; k++) {
        int c = k * 8 + lc;
        qf[k][0] = __float_as_uint(Qg[rq * 64 + c]);
        qf[k][1] = __float_as_uint(Qg[(rq + 8) * 64 + c]);
        qf[k][2] = __float_as_uint(Qg[rq * 64 + c + 4]);
        qf[k][3] = __float_as_uint(Qg[(rq + 8) * 64 + c + 4]);
    }

    float oacc[8][4];
#pragma unroll
    for (int nt = 0; nt < 8; nt++)
#pragma unroll
        for (int i = 0; i < 4; i++) oacc[nt][i] = 0.f;
    float m_i[2] = {-INFINITY, -INFINITY};
    float l_i[2] = {0.f, 0.f};

    const int lkey = tid >> 4, lkd = (tid & 15) << 2;   // K loader
    const int vkey = tid & 31, vd0 = (tid >> 5) << 2;   // V loader (transpose)

    for (int kt = 0; kt < LL / 32; kt++) {
        const int kb = kt << 5;
        __syncthreads();
        // K tile [key][d]
#pragma unroll
        for (int p = 0; p < 2; p++) {
            float4 kv = *(const float4*)(Kg + (size_t)(kb + lkey + p * 16) * 64 + lkd);
            *(float4*)&Ks[(lkey + p * 16) * 68 + lkd] = kv;
        }
        // V tile transposed [d][key]
#pragma unroll
        for (int p = 0; p < 2; p++) {
            int d0 = vd0 + p * 32;
            float4 vv = *(const float4*)(Vg + (size_t)(kb + vkey) * 64 + d0);
            Vs[(d0 + 0) * 36 + vkey] = vv.x; Vs[(d0 + 1) * 36 + vkey] = vv.y;
            Vs[(d0 + 2) * 36 + vkey] = vv.z; Vs[(d0 + 3) * 36 + vkey] = vv.w;
        }
        __syncthreads();

        // S = Q K^T (16 x 32 per warp)
        float sacc[4][4];
#pragma unroll
        for (int nt = 0; nt < 4; nt++)
#pragma unroll
            for (int i = 0; i < 4; i++) sacc[nt][i] = 0.f;
        const unsigned* Ku = (const unsigned*)Ks;
#pragma unroll
        for (int k = 0; k < 8; k++) {
            unsigned b[4][2];
#pragma unroll
            for (int nt = 0; nt < 4; nt++) {
                int bb = (nt * 8 + lr4) * 68 + k * 8 + lc;
                b[nt][0] = Ku[bb]; b[nt][1] = Ku[bb + 4];
            }
#pragma unroll
            for (int nt = 0; nt < 4; nt++) mma_tf32(sacc[nt], qf[k], b[nt]);
        }

        // Online softmax per row-half; stage tf32 P into per-warp smem region
#pragma unroll
        for (int h2 = 0; h2 < 2; h2++) {
            float rm = -INFINITY;
#pragma unroll
            for (int nt = 0; nt < 4; nt++)
                rm = fmaxf(rm, fmaxf(sacc[nt][h2 * 2], sacc[nt][h2 * 2 + 1]));
            rm = fmaxf(rm, __shfl_xor_sync(0xffffffffu, rm, 1));
            rm = fmaxf(rm, __shfl_xor_sync(0xffffffffu, rm, 2));
            float mn = fmaxf(m_i[h2], rm);
            float corr = __expf(m_i[h2] - mn);
            m_i[h2] = mn;
            float rs = 0.f;
#pragma unroll
            for (int nt = 0; nt < 4; nt++) {
                float p0 = __expf(sacc[nt][h2 * 2] - mn);
                float p1 = __expf(sacc[nt][h2 * 2 + 1] - mn);
                rs += p0 + p1;
                float2 pv;
                pv.x = __uint_as_float(f2tf32(p0));
                pv.y = __uint_as_float(f2tf32(p1));
                *(float2*)&Ps[(rq + h2 * 8) * 36 + nt * 8 + lc * 2] = pv;
            }
            rs += __shfl_xor_sync(0xffffffffu, rs, 1);
            rs += __shfl_xor_sync(0xffffffffu, rs, 2);
            l_i[h2] = l_i[h2] * corr + rs;
#pragma unroll
            for (int nt = 0; nt < 8; nt++) {
                oacc[nt][h2 * 2]     *= corr;
                oacc[nt][h2 * 2 + 1] *= corr;
            }
        }
        __syncwarp();

        // O += P V (16 x 64 per warp)
        const unsigned* Pu = (const unsigned*)Ps;
        const unsigned* Vu = (const unsigned*)Vs;
#pragma unroll
        for (int k = 0; k < 4; k++) {
            unsigned a[4];
            int ab = rq * 36 + k * 8 + lc;
            a[0] = Pu[ab];           a[1] = Pu[ab + 8 * 36];
            a[2] = Pu[ab + 4];       a[3] = Pu[ab + 8 * 36 + 4];
#pragma unroll
            for (int nt = 0; nt < 8; nt++) {
                unsigned b[2];
                int bb = (nt * 8 + lr4) * 36 + k * 8 + lc;
                b[0] = Vu[bb]; b[1] = Vu[bb + 4];
                mma_tf32(oacc[nt], a, b);
            }
        }
    }

    // Epilogue: 1/l, gate, tf32 round, scatter to (b, l, h*64+d)
    const int b = bh >> 4, h = bh & 15;
#pragma unroll
    for (int h2 = 0; h2 < 2; h2++) {
        int q = qbase + rq + h2 * 8;
        float sc = g_gate[b * LL + q] / l_i[h2];
        float* dst = g_o + ((size_t)(b * LL + q)) * DD + h * HD;
#pragma unroll
        for (int nt = 0; nt < 8; nt++) {
            int d = nt * 8 + lc * 2;
            float2 ov;
            ov.x = __uint_as_float(f2tf32(oacc[nt][h2 * 2] * sc));
            ov.y = __uint_as_float(f2tf32(oacc[nt][h2 * 2 + 1] * sc));
            *(float2*)(dst + d) = ov;
        }
    }
}

// ---------------------------------------------------------------------------
// Out GEMM (tensor core): C[m][n] = sum_k g_o[m][k]*W[n][k] + bias[n]
// M=4096, N=1024, K=1024
// ---------------------------------------------------------------------------
__global__ __launch_bounds__(256, 2) void out_gemm_tc(
    const float* __restrict__ bias, float* __restrict__ C)
{
    __shared__ float As[128 * 20];
    __shared__ float Bs[128 * 20];
    const int tid = threadIdx.x, lane = tid & 31, wid = tid >> 5;
    const int wm = (wid & 1) << 6, wn = (wid >> 1) << 5;
    const int bm = blockIdx.y << 7, bn = blockIdx.x << 7;
    const int lr4 = lane >> 2, lc = lane & 3;

    float acc[4][4][4];
#pragma unroll
    for (int mt = 0; mt < 4; mt++)
#pragma unroll
        for (int nt = 0; nt < 4; nt++)
#pragma unroll
            for (int i = 0; i < 4; i++) acc[mt][nt][i] = 0.f;

    const int row = tid >> 2, kk = (tid & 3) << 2;
    const float* Ag = g_o + (size_t)(bm + row) * DD + kk;
    const float* Bg = g_wo + (size_t)(bn + row) * DD + kk;

    for (int k0 = 0; k0 < DD; k0 += 16) {
        float4 a0 = *(const float4*)(Ag + k0);
        float4 a1 = *(const float4*)(Ag + k0 + (size_t)64 * DD);
        float4 b0 = *(const float4*)(Bg + k0);
        float4 b1 = *(const float4*)(Bg + k0 + (size_t)64 * DD);
        __syncthreads();
        *(float4*)&As[row * 20 + kk]        = a0;
        *(float4*)&As[(row + 64) * 20 + kk] = a1;
        *(float4*)&Bs[row * 20 + kk]        = b0;
        *(float4*)&Bs[(row + 64) * 20 + kk] = b1;
        __syncthreads();
        const unsigned* Au = (const unsigned*)As;
        const unsigned* Bu = (const unsigned*)Bs;
#pragma unroll
        for (int ks = 0; ks < 16; ks += 8) {
            unsigned a[4][4], b[4][2];
#pragma unroll
            for (int mt = 0; mt < 4; mt++) {
                int base = (wm + mt * 16 + lr4) * 20 + ks + lc;
                a[mt][0] = Au[base];       a[mt][1] = Au[base + 160];
                a[mt][2] = Au[base + 4];   a[mt][3] = Au[base + 164];
            }
#pragma unroll
            for (int nt = 0; nt < 4; nt++) {
                int bb = (wn + nt * 8 + lr4) * 20 + ks + lc;
                b[nt][0] = Bu[bb]; b[nt][1] = Bu[bb + 4];
            }
#pragma unroll
            for (int mt = 0; mt < 4; mt++)
#pragma unroll
                for (int nt = 0; nt < 4; nt++) mma_tf32(acc[mt][nt], a[mt], b[nt]);
        }
    }

#pragma unroll
    for (int mt = 0; mt < 4; mt++)
#pragma unroll
        for (int nt = 0; nt < 4; nt++) {
            int m = bm + wm + mt * 16 + lr4;
            int n = bn + wn + (nt << 3) + (lc << 1);
            float2 r0v, r1v;
            r0v.x = acc[mt][nt][0] + bias[n];
            r0v.y = acc[mt][nt][1] + bias[n + 1];
            r1v.x = acc[mt][nt][2] + bias[n];
            r1v.y = acc[mt][nt][3] + bias[n + 1];
            *(float2*)&C[(size_t)m * DD + n]       = r0v;
            *(float2*)&C[(size_t)(m + 8) * DD + n] = r1v;
        }
}

// ---------------------------------------------------------------------------
extern "C" void kernel_launch(void* const* d_in, const int* in_sizes, int n_in,
                              void* d_out, int out_size)
{
    const float* x    = (const float*)d_in[0];
    const float* G    = (const float*)d_in[1];
    const float* qkvw = (const float*)d_in[2];
    const float* outw = (const float*)d_in[3];
    const float* outb = (const float*)d_in[4];
    const float* gsc  = (const float*)d_in[5];
    const float* ltm  = (const float*)d_in[6];
    float* out = (float*)d_out;

    float* xt; cudaGetSymbolAddress((void**)&xt, g_xt);
    float* wq; cudaGetSymbolAddress((void**)&wq, g_wq);
    float* wo; cudaGetSymbolAddress((void**)&wo, g_wo);

    cvt_tf32_kernel<<<(MM * DD) / 256, 256>>>(x, xt, MM * DD);
    cvt_tf32_kernel<<<(N_QKV * DD) / 256, 256>>>(qkvw, wq, N_QKV * DD);
    cvt_tf32_kernel<<<(DD * DD) / 256, 256>>>(outw, wo, DD * DD);

    dim3 g1(N_QKV / 128, MM / 128);   // (24, 32)
    qkv_gemm_tc<<<g1, 256>>>();

    gate_kernel<<<BB, 256>>>(G, gsc, ltm);

    dim3 g2(LL / 128, BB * HH);       // (16, 32)
    attn_tc<<<g2, 256>>>();

    dim3 g3(DD / 128, MM / 128);      // (8, 32)
    out_gemm_tc<<<g3, 256>>>(outb, out);
}